// round 7
// baseline (speedup 1.0000x reference)
#include <cuda_runtime.h>
#include <cuda_fp16.h>
#include <cstdint>
#include <cstddef>

#define Bc 8
#define Tc 2048
#define Dc 256
#define Hc 4
#define FFNc 1024

// ---------------- scratch (static device arrays) ----------------
__device__ __half g_xh[(size_t)Bc * Tc * Dc];
__device__ __half g_qkvh[(size_t)Bc * Tc * 3 * Dc];
__device__ __half g_vth[(size_t)Bc * Hc * 64 * Tc];     // V^T fp16 [bh][d][k]
__device__ __half g_attnh[(size_t)Bc * Tc * Dc];
__device__ __half g_hh[(size_t)Bc * Tc * Dc];
__device__ __half g_fh[(size_t)Bc * Tc * FFNc];
__device__ __half g_wqkvh[3 * Dc * Dc];
__device__ __half g_woh[Dc * Dc];
__device__ __half g_w1h[FFNc * Dc];
__device__ __half g_w2h[Dc * FFNc];
__device__ float g_h[(size_t)Bc * Tc * Dc];
__device__ float g_hraw[Bc * Tc];

// ---------------- helpers ----------------
__device__ __forceinline__ uint32_t s2u(const void* p) {
    uint32_t a;
    asm("{ .reg .u64 t; cvta.to.shared.u64 t, %1; cvt.u32.u64 %0, t; }" : "=r"(a) : "l"(p));
    return a;
}
__device__ __forceinline__ float ex2(float x) {
    float r;
    asm("ex2.approx.ftz.f32 %0, %1;" : "=f"(r) : "f"(x));
    return r;
}
#define EXPC 0.18033688011112042f   // 0.125 * log2(e)
#define CP_ASYNC16(dst, src) \
    asm volatile("cp.async.cg.shared.global [%0], [%1], 16;" :: "r"(dst), "l"(src))

__device__ __forceinline__ void ldm_x4(uint32_t* r, uint32_t addr) {
    asm volatile("ldmatrix.sync.aligned.m8n8.x4.shared.b16 {%0,%1,%2,%3}, [%4];"
                 : "=r"(r[0]), "=r"(r[1]), "=r"(r[2]), "=r"(r[3]) : "r"(addr));
}
__device__ __forceinline__ void mma16816(float* c, const uint32_t* a, const uint32_t* b) {
    asm volatile("mma.sync.aligned.m16n8k16.row.col.f32.f16.f16.f32 "
                 "{%0,%1,%2,%3}, {%4,%5,%6,%7}, {%8,%9}, {%0,%1,%2,%3};"
                 : "+f"(c[0]), "+f"(c[1]), "+f"(c[2]), "+f"(c[3])
                 : "r"(a[0]), "r"(a[1]), "r"(a[2]), "r"(a[3]), "r"(b[0]), "r"(b[1]));
}

// ---------------- merged attention, register-resident weights ----------------
// 8 warps x 16 q-rows; per warp full k range. E never touches smem.
__global__ __launch_bounds__(256, 2) void attn2_k(const __half* __restrict__ qkvh,
                                                  const float* __restrict__ mask) {
    extern __shared__ char sm[];
    const uint32_t S0 = s2u(sm);
    const uint32_t Qs = S0, Ks = S0 + 16384, Vs = S0 + 32768;
    float* msk = (float*)(sm + 49152);       // 2048 floats: additive offsets 0 / -1000
    const int tid = threadIdx.x, lane = tid & 31, wid = tid >> 5;
    const int bh = blockIdx.y, b = bh >> 2, h = bh & 3;
    const int m0 = blockIdx.x * 128;
    const int r0 = wid * 16;
    const int rr = r0 + (lane >> 2);                 // this thread's first q row
    const int ccol = 2 * (lane & 3);

    for (int i = tid; i < Tc; i += 256) msk[i] = (mask[b * Tc + i] > 0.5f) ? -1000.f : 0.f;

    {   // Q tile
        const __half* q0 = qkvh + ((size_t)(b * Tc + m0)) * 768 + h * 64;
#pragma unroll
        for (int i = 0; i < 4; ++i) {
            int ch = i * 256 + tid, r = ch >> 3, c = ch & 7;
            CP_ASYNC16(Qs + r * 128 + ((c ^ (r & 7)) << 4), q0 + (size_t)r * 768 + c * 8);
        }
    }
    asm volatile("cp.async.commit_group;");
    auto loadK = [&](int kt, int buf) {
        const __half* kg = qkvh + ((size_t)(b * Tc + kt * 64)) * 768 + 256 + h * 64;
#pragma unroll
        for (int i = 0; i < 2; ++i) {
            int ch = i * 256 + tid, r = ch >> 3, c = ch & 7;
            CP_ASYNC16(Ks + buf * 8192 + r * 128 + ((c ^ (r & 7)) << 4), kg + (size_t)r * 768 + c * 8);
        }
    };
    auto loadKV = [&](int kt, int buf) {
        const int k0 = kt * 64;
        const __half* kg = qkvh + ((size_t)(b * Tc + k0)) * 768 + 256 + h * 64;
        const __half* vg = g_vth + (size_t)bh * 64 * Tc + k0;
#pragma unroll
        for (int i = 0; i < 2; ++i) {
            int ch = i * 256 + tid, r = ch >> 3, c = ch & 7;
            uint32_t off = r * 128 + ((c ^ (r & 7)) << 4);
            CP_ASYNC16(Ks + buf * 8192 + off, kg + (size_t)r * 768 + c * 8);
            CP_ASYNC16(Vs + buf * 8192 + off, vg + (size_t)r * Tc + c * 8);
        }
    };
    loadK(0, 0);
    asm volatile("cp.async.commit_group;");

    // hoist Q fragments (invariant across all kt)
    asm volatile("cp.async.wait_group 1;");
    __syncthreads();
    uint32_t qf[4][4];
    {
        const int m = r0 + (lane & 15);
#pragma unroll
        for (int ks = 0; ks < 4; ++ks) {
            const int ck = ks * 2 + (lane >> 4);
            ldm_x4(qf[ks], Qs + m * 128 + ((ck ^ (m & 7)) << 4));
        }
    }

    // compute S accumulators for one kt from K smem buffer
    auto stileS = [&](uint32_t cK, float (&sacc)[8][4]) {
#pragma unroll
        for (int nt = 0; nt < 8; ++nt)
#pragma unroll
            for (int i = 0; i < 4; ++i) sacc[nt][i] = 0.f;
#pragma unroll
        for (int ks = 0; ks < 4; ++ks) {
            const int ck = ks * 2 + (lane >> 4);
            uint32_t bk[8][2];
#pragma unroll
            for (int g = 0; g < 4; ++g) {
                uint32_t r4[4];
                const int n = g * 16 + (lane & 15);
                ldm_x4(r4, cK + n * 128 + ((ck ^ (n & 7)) << 4));
                bk[2 * g][0] = r4[0]; bk[2 * g][1] = r4[2];
                bk[2 * g + 1][0] = r4[1]; bk[2 * g + 1][1] = r4[3];
            }
#pragma unroll
            for (int nt = 0; nt < 8; ++nt) mma16816(sacc[nt], qf[ks], bk[nt]);
        }
    };

    // ---- loop A: denominators ----
    float dacc0 = 0.f, dacc1 = 0.f;
    for (int kt = 0; kt < 32; ++kt) {
        const int buf = kt & 1;
        asm volatile("cp.async.wait_group 0;");
        __syncthreads();
        float sacc[8][4];
        stileS(Ks + buf * 8192, sacc);
        if (kt + 1 < 32) {
            loadK(kt + 1, buf ^ 1);
            asm volatile("cp.async.commit_group;");
        }
        const int k0 = kt * 64;
#pragma unroll
        for (int nt = 0; nt < 8; ++nt) {
            const float2 m2 = *(const float2*)&msk[k0 + nt * 8 + ccol];
            dacc0 += ex2(fmaf(sacc[nt][0], EXPC, m2.x)) + ex2(fmaf(sacc[nt][1], EXPC, m2.y));
            dacc1 += ex2(fmaf(sacc[nt][2], EXPC, m2.x)) + ex2(fmaf(sacc[nt][3], EXPC, m2.y));
        }
    }
    dacc0 += __shfl_xor_sync(~0u, dacc0, 1); dacc0 += __shfl_xor_sync(~0u, dacc0, 2);
    dacc1 += __shfl_xor_sync(~0u, dacc1, 1); dacc1 += __shfl_xor_sync(~0u, dacc1, 2);
    const float l2r0 = -__log2f(dacc0);
    const float l2r1 = -__log2f(dacc1);

    // ---- loop B: normalized weights (registers) -> PV + halting colsum ----
    loadKV(0, 0);
    asm volatile("cp.async.commit_group;");
    float pacc[8][4];
#pragma unroll
    for (int dt = 0; dt < 8; ++dt)
#pragma unroll
        for (int i = 0; i < 4; ++i) pacc[dt][i] = 0.f;

    for (int kt = 0; kt < 32; ++kt) {
        const int buf = kt & 1;
        asm volatile("cp.async.wait_group 0;");
        __syncthreads();
        float sacc[8][4];
        stileS(Ks + buf * 8192, sacc);
        if (kt + 1 < 32) {
            loadKV(kt + 1, buf ^ 1);
            asm volatile("cp.async.commit_group;");
        }
        const int k0 = kt * 64;
        uint32_t wlo[8], whi[8];
#pragma unroll
        for (int nt = 0; nt < 8; ++nt) {
            const float2 m2 = *(const float2*)&msk[k0 + nt * 8 + ccol];
            float w0 = ex2(fmaf(sacc[nt][0], EXPC, m2.x + l2r0));
            float w1 = ex2(fmaf(sacc[nt][1], EXPC, m2.y + l2r0));
            float w2 = ex2(fmaf(sacc[nt][2], EXPC, m2.x + l2r1));
            float w3 = ex2(fmaf(sacc[nt][3], EXPC, m2.y + l2r1));
            __half2 hl = __floats2half2_rn(w0, w1);
            __half2 hh = __floats2half2_rn(w2, w3);
            wlo[nt] = *(uint32_t*)&hl;
            whi[nt] = *(uint32_t*)&hh;
            // column sums for halting (reduce over this warp's 16 rows)
            float v0 = w0 + w2, v1 = w1 + w3;
            v0 += __shfl_xor_sync(~0u, v0, 4); v0 += __shfl_xor_sync(~0u, v0, 8);
            v0 += __shfl_xor_sync(~0u, v0, 16);
            v1 += __shfl_xor_sync(~0u, v1, 4); v1 += __shfl_xor_sync(~0u, v1, 8);
            v1 += __shfl_xor_sync(~0u, v1, 16);
            if (lane < 4) {
                atomicAdd(&g_hraw[b * Tc + k0 + nt * 8 + 2 * lane], 0.25f * v0);
                atomicAdd(&g_hraw[b * Tc + k0 + nt * 8 + 2 * lane + 1], 0.25f * v1);
            }
        }
        // PV: A operand straight from registers
        const uint32_t cV = Vs + buf * 8192;
#pragma unroll
        for (int kc = 0; kc < 4; ++kc) {
            uint32_t af[4] = {wlo[2 * kc], whi[2 * kc], wlo[2 * kc + 1], whi[2 * kc + 1]};
            const int ck = kc * 2 + (lane >> 4);
            uint32_t bv[8][2];
#pragma unroll
            for (int g = 0; g < 4; ++g) {
                uint32_t r4[4];
                const int n = g * 16 + (lane & 15);
                ldm_x4(r4, cV + n * 128 + ((ck ^ (n & 7)) << 4));
                bv[2 * g][0] = r4[0]; bv[2 * g][1] = r4[2];
                bv[2 * g + 1][0] = r4[1]; bv[2 * g + 1][1] = r4[3];
            }
#pragma unroll
            for (int dt = 0; dt < 8; ++dt) mma16816(pacc[dt], af, bv[dt]);
        }
    }

    // write normalized attention
#pragma unroll
    for (int dt = 0; dt < 8; ++dt) {
        const int c = dt * 8 + ccol;
        *(__half2*)(g_attnh + (size_t)(b * Tc + m0 + rr) * Dc + h * 64 + c) =
            __floats2half2_rn(pacc[dt][0], pacc[dt][1]);
        *(__half2*)(g_attnh + (size_t)(b * Tc + m0 + rr + 8) * Dc + h * 64 + c) =
            __floats2half2_rn(pacc[dt][2], pacc[dt][3]);
    }
}

// ---------------- fp16 mma.sync GEMM core (BM=128, BN=128) ----------------
__device__ __forceinline__ void gemm_core128(const __half* __restrict__ Ag, int lda,
                                             const __half* __restrict__ Bg, int ldb,
                                             int K, int m0, int n0,
                                             float (&acc)[4][4][4]) {
    extern __shared__ char smem_raw[];
    const int tid = threadIdx.x, lane = tid & 31, wid = tid >> 5;
    const int wm = (wid >> 2) * 64;
    const int wn = (wid & 3) * 32;
    const uint32_t sA = s2u(smem_raw);
    const uint32_t sB = sA + 2 * 128 * 128;
    const int NKT = K >> 6;

#pragma unroll
    for (int mt = 0; mt < 4; ++mt)
#pragma unroll
        for (int nt = 0; nt < 4; ++nt)
#pragma unroll
            for (int i = 0; i < 4; ++i) acc[mt][nt][i] = 0.f;

    auto loadA = [&](int kt, int buf) {
        const __half* s0 = Ag + (size_t)m0 * lda + kt * 64;
        uint32_t d0 = sA + buf * (128 * 128);
#pragma unroll
        for (int i = 0; i < 4; ++i) {
            int ch = i * 256 + tid, r = ch >> 3, c = ch & 7;
            CP_ASYNC16(d0 + r * 128 + ((c ^ (r & 7)) << 4), s0 + (size_t)r * lda + c * 8);
        }
    };
    auto loadB = [&](int kt, int buf) {
        const __half* s0 = Bg + (size_t)n0 * ldb + kt * 64;
        uint32_t d0 = sB + buf * (128 * 128);
#pragma unroll
        for (int i = 0; i < 4; ++i) {
            int ch = i * 256 + tid, r = ch >> 3, c = ch & 7;
            CP_ASYNC16(d0 + r * 128 + ((c ^ (r & 7)) << 4), s0 + (size_t)r * ldb + c * 8);
        }
    };

    loadA(0, 0); loadB(0, 0);
    asm volatile("cp.async.commit_group;");

    for (int t = 0; t < NKT; ++t) {
        const int buf = t & 1;
        if (t + 1 < NKT) {
            loadA(t + 1, buf ^ 1); loadB(t + 1, buf ^ 1);
            asm volatile("cp.async.commit_group;");
            asm volatile("cp.async.wait_group 1;");
        } else {
            asm volatile("cp.async.wait_group 0;");
        }
        __syncthreads();
        const uint32_t cA = sA + buf * (128 * 128);
        const uint32_t cB = sB + buf * (128 * 128);
#pragma unroll
        for (int ks = 0; ks < 4; ++ks) {
            uint32_t af[4][4];
#pragma unroll
            for (int mt = 0; mt < 4; ++mt) {
                int m = wm + mt * 16 + (lane & 15);
                int ck = ks * 2 + (lane >> 4);
                ldm_x4(af[mt], cA + m * 128 + ((ck ^ (m & 7)) << 4));
            }
            uint32_t bf[4][2];
#pragma unroll
            for (int g = 0; g < 2; ++g) {
                uint32_t r4[4];
                int n = wn + g * 16 + (lane & 15);
                int ck = ks * 2 + (lane >> 4);
                ldm_x4(r4, cB + n * 128 + ((ck ^ (n & 7)) << 4));
                bf[2 * g][0] = r4[0]; bf[2 * g][1] = r4[2];
                bf[2 * g + 1][0] = r4[1]; bf[2 * g + 1][1] = r4[3];
            }
#pragma unroll
            for (int mt = 0; mt < 4; ++mt)
#pragma unroll
                for (int nt = 0; nt < 4; ++nt) mma16816(acc[mt][nt], af[mt], bf[nt]);
        }
        __syncthreads();
    }
}

__global__ __launch_bounds__(256) void gemm_proj_k(const __half* __restrict__ A,
                                                   const __half* __restrict__ Bw,
                                                   const float* __restrict__ bias,
                                                   __half* __restrict__ Ch,
                                                   int lda, int ldb, int ldc, int K, int relu) {
    float acc[4][4][4];
    const int m0 = blockIdx.y * 128, n0 = blockIdx.x * 128;
    gemm_core128(A, lda, Bw, ldb, K, m0, n0, acc);
    const int lane = threadIdx.x & 31, wid = threadIdx.x >> 5;
    const int wm = (wid >> 2) * 64, wn = (wid & 3) * 32;
#pragma unroll
    for (int mt = 0; mt < 4; ++mt) {
        int r = m0 + wm + mt * 16 + (lane >> 2);
#pragma unroll
        for (int nt = 0; nt < 4; ++nt) {
            int col = n0 + wn + nt * 8 + 2 * (lane & 3);
            float bx = __ldg(bias + col), by = __ldg(bias + col + 1);
            float v0 = acc[mt][nt][0] + bx, v1 = acc[mt][nt][1] + by;
            float v2 = acc[mt][nt][2] + bx, v3 = acc[mt][nt][3] + by;
            if (relu) {
                v0 = fmaxf(v0, 0.f); v1 = fmaxf(v1, 0.f);
                v2 = fmaxf(v2, 0.f); v3 = fmaxf(v3, 0.f);
            }
            *(__half2*)(Ch + (size_t)r * ldc + col) = __floats2half2_rn(v0, v1);
            *(__half2*)(Ch + (size_t)(r + 8) * ldc + col) = __floats2half2_rn(v2, v3);
        }
    }
}

// ---------------- GEMM (BM=64, BN=256=N) + bias + residual + LayerNorm ----------------
__global__ __launch_bounds__(256) void gemm_ln_k(const __half* __restrict__ A,
                                                 const __half* __restrict__ Bw,
                                                 const float* __restrict__ bias,
                                                 const float* __restrict__ res,
                                                 const float* __restrict__ gamma,
                                                 const float* __restrict__ beta,
                                                 float* __restrict__ outf,
                                                 __half* __restrict__ outh,
                                                 int lda, int K) {
    extern __shared__ char sm[];
    const uint32_t sA = s2u(sm);               // 2 x 8192
    const uint32_t sB = sA + 16384;            // 2 x 32768
    float* sred = (float*)(sm + 16384 + 65536);
    float* sqred = sred + 64;
    const int tid = threadIdx.x, lane = tid & 31, wid = tid >> 5;
    const int m0 = blockIdx.x * 64;
    const int wm = (wid >> 2) * 32, wn = (wid & 3) * 64;
    const int NKT = K >> 6;

    float acc[2][8][4];
#pragma unroll
    for (int mt = 0; mt < 2; ++mt)
#pragma unroll
        for (int nt = 0; nt < 8; ++nt)
#pragma unroll
            for (int i = 0; i < 4; ++i) acc[mt][nt][i] = 0.f;

    auto loadA = [&](int kt, int buf) {
        const __half* s0 = A + (size_t)m0 * lda + kt * 64;
        uint32_t d0 = sA + buf * 8192;
#pragma unroll
        for (int i = 0; i < 2; ++i) {
            int ch = i * 256 + tid, r = ch >> 3, c = ch & 7;
            CP_ASYNC16(d0 + r * 128 + ((c ^ (r & 7)) << 4), s0 + (size_t)r * lda + c * 8);
        }
    };
    auto loadB = [&](int kt, int buf) {
        const __half* s0 = Bw + kt * 64;
        uint32_t d0 = sB + buf * 32768;
#pragma unroll
        for (int i = 0; i < 8; ++i) {
            int ch = i * 256 + tid, r = ch >> 3, c = ch & 7;
            CP_ASYNC16(d0 + r * 128 + ((c ^ (r & 7)) << 4), s0 + (size_t)r * K + c * 8);
        }
    };

    loadA(0, 0); loadB(0, 0);
    asm volatile("cp.async.commit_group;");

    for (int t = 0; t < NKT; ++t) {
        const int buf = t & 1;
        if (t + 1 < NKT) {
            loadA(t + 1, buf ^ 1); loadB(t + 1, buf ^ 1);
            asm volatile("cp.async.commit_group;");
            asm volatile("cp.async.wait_group 1;");
        } else {
            asm volatile("cp.async.wait_group 0;");
        }
        __syncthreads();
        const uint32_t cA = sA + buf * 8192;
        const uint32_t cB = sB + buf * 32768;
#pragma unroll
        for (int ks = 0; ks < 4; ++ks) {
            const int ck = ks * 2 + (lane >> 4);
            uint32_t af[2][4];
#pragma unroll
            for (int mt = 0; mt < 2; ++mt) {
                int m = wm + mt * 16 + (lane & 15);
                ldm_x4(af[mt], cA + m * 128 + ((ck ^ (m & 7)) << 4));
            }
            uint32_t bf[8][2];
#pragma unroll
            for (int g = 0; g < 4; ++g) {
                uint32_t r4[4];
                int n = wn + g * 16 + (lane & 15);
                ldm_x4(r4, cB + n * 128 + ((ck ^ (n & 7)) << 4));
                bf[2 * g][0] = r4[0]; bf[2 * g][1] = r4[2];
                bf[2 * g + 1][0] = r4[1]; bf[2 * g + 1][1] = r4[3];
            }
#pragma unroll
            for (int mt = 0; mt < 2; ++mt)
#pragma unroll
                for (int nt = 0; nt < 8; ++nt) mma16816(acc[mt][nt], af[mt], bf[nt]);
        }
        __syncthreads();
    }

    // ---- epilogue: bias + residual, LN stats, normalize ----
    if (tid < 64) { sred[tid] = 0.f; sqred[tid] = 0.f; }
    __syncthreads();
#pragma unroll
    for (int mt = 0; mt < 2; ++mt) {
        const int r = wm + mt * 16 + (lane >> 2);
        float s0 = 0.f, sq0 = 0.f, s1 = 0.f, sq1 = 0.f;
#pragma unroll
        for (int nt = 0; nt < 8; ++nt) {
            const int col = wn + nt * 8 + 2 * (lane & 3);
            float bx = __ldg(bias + col), by = __ldg(bias + col + 1);
            float2 r0 = *(const float2*)(res + (size_t)(m0 + r) * Dc + col);
            float2 r1 = *(const float2*)(res + (size_t)(m0 + r + 8) * Dc + col);
            float v0 = acc[mt][nt][0] + bx + r0.x;
            float v1 = acc[mt][nt][1] + by + r0.y;
            float v2 = acc[mt][nt][2] + bx + r1.x;
            float v3 = acc[mt][nt][3] + by + r1.y;
            acc[mt][nt][0] = v0; acc[mt][nt][1] = v1;
            acc[mt][nt][2] = v2; acc[mt][nt][3] = v3;
            s0 += v0 + v1; sq0 += v0 * v0 + v1 * v1;
            s1 += v2 + v3; sq1 += v2 * v2 + v3 * v3;
        }
        s0 += __shfl_xor_sync(~0u, s0, 1); s0 += __shfl_xor_sync(~0u, s0, 2);
        sq0 += __shfl_xor_sync(~0u, sq0, 1); sq0 += __shfl_xor_sync(~0u, sq0, 2);
        s1 += __shfl_xor_sync(~0u, s1, 1); s1 += __shfl_xor_sync(~0u, s1, 2);
        sq1 += __shfl_xor_sync(~0u, sq1, 1); sq1 += __shfl_xor_sync(~0u, sq1, 2);
        if ((lane & 3) == 0) {
            atomicAdd(&sred[r], s0); atomicAdd(&sqred[r], sq0);
            atomicAdd(&sred[r + 8], s1); atomicAdd(&sqred[r + 8], sq1);
        }
    }
    __syncthreads();
#pragma unroll
    for (int mt = 0; mt < 2; ++mt) {
        const int r = wm + mt * 16 + (lane >> 2);
        const float mean0 = sred[r] * (1.f / Dc);
        const float rstd0 = rsqrtf(sqred[r] * (1.f / Dc) - mean0 * mean0 + 1e-5f);
        const float mean1 = sred[r + 8] * (1.f / Dc);
        const float rstd1 = rsqrtf(sqred[r + 8] * (1.f / Dc) - mean1 * mean1 + 1e-5f);
#pragma unroll
        for (int nt = 0; nt < 8; ++nt) {
            const int col = wn + nt * 8 + 2 * (lane & 3);
            float gx = __ldg(gamma + col), gy = __ldg(gamma + col + 1);
            float bx = __ldg(beta + col), by = __ldg(beta + col + 1);
            float o0 = (acc[mt][nt][0] - mean0) * rstd0 * gx + bx;
            float o1 = (acc[mt][nt][1] - mean0) * rstd0 * gy + by;
            float o2 = (acc[mt][nt][2] - mean1) * rstd1 * gx + bx;
            float o3 = (acc[mt][nt][3] - mean1) * rstd1 * gy + by;
            *(float2*)(outf + (size_t)(m0 + r) * Dc + col) = make_float2(o0, o1);
            *(float2*)(outf + (size_t)(m0 + r + 8) * Dc + col) = make_float2(o2, o3);
            if (outh) {
                *(__half2*)(outh + (size_t)(m0 + r) * Dc + col) = __floats2half2_rn(o0, o1);
                *(__half2*)(outh + (size_t)(m0 + r + 8) * Dc + col) = __floats2half2_rn(o2, o3);
            }
        }
    }
}

// ---------------- V transpose ----------------
__global__ __launch_bounds__(256) void vt_pack(const __half* __restrict__ qkvh) {
    __shared__ __half tile[64][72];
    const int bh = blockIdx.y, b = bh >> 2, h = bh & 3;
    const int k0 = blockIdx.x * 64;
    const int t = threadIdx.x;
#pragma unroll
    for (int i = 0; i < 16; ++i) {
        int idx = t + i * 256, kk = idx >> 6, d = idx & 63;
        tile[kk][d] = qkvh[(size_t)(b * Tc + k0 + kk) * 768 + 512 + h * 64 + d];
    }
    __syncthreads();
#pragma unroll
    for (int i = 0; i < 16; ++i) {
        int idx = t + i * 256, d = idx >> 6, kk = idx & 63;
        g_vth[(size_t)bh * 64 * Tc + (size_t)d * Tc + k0 + kk] = tile[kk][d];
    }
}

// ---------------- one merged pack kernel ----------------
#define SEG0 2097152u
#define SEG1 2195456u
#define SEG2 2228224u
#define SEG3 2359296u
#define SEG4 2490368u
__global__ __launch_bounds__(256) void pack_all(const float* __restrict__ x,
                                                const float* __restrict__ Wqkv,
                                                const float* __restrict__ Wo,
                                                const float* __restrict__ W1,
                                                const float* __restrict__ W2) {
    uint32_t i = blockIdx.x * 256 + threadIdx.x;
    if (i < Bc * Tc / 2) ((float2*)g_hraw)[i] = make_float2(0.f, 0.f);
    const float2* s;
    __half2* d;
    uint32_t off;
    if (i < SEG0)      { s = (const float2*)x;    d = (__half2*)g_xh;    off = i; }
    else if (i < SEG1) { s = (const float2*)Wqkv; d = (__half2*)g_wqkvh; off = i - SEG0; }
    else if (i < SEG2) { s = (const float2*)Wo;   d = (__half2*)g_woh;   off = i - SEG1; }
    else if (i < SEG3) { s = (const float2*)W1;   d = (__half2*)g_w1h;   off = i - SEG2; }
    else if (i < SEG4) { s = (const float2*)W2;   d = (__half2*)g_w2h;   off = i - SEG3; }
    else return;
    float2 v = s[off];
    d[off] = __floats2half2_rn(v.x, v.y);
}

__global__ __launch_bounds__(256) void halting_k(const float* __restrict__ mask, float* __restrict__ out) {
    const int b = blockIdx.x;
    const int t = threadIdx.x;
    __shared__ float es[Tc];
    __shared__ float redm[8], reds[8];
    float lmax = -3.4e38f;
    for (int k = t; k < Tc; k += 256) {
        float v = g_hraw[b * Tc + k] + mask[b * Tc + k] * (-1e10f);
        es[k] = v;
        lmax = fmaxf(lmax, v);
    }
#pragma unroll
    for (int o = 16; o; o >>= 1) lmax = fmaxf(lmax, __shfl_xor_sync(~0u, lmax, o));
    if ((t & 31) == 0) redm[t >> 5] = lmax;
    __syncthreads();
    float bmax = redm[0];
#pragma unroll
    for (int j = 1; j < 8; ++j) bmax = fmaxf(bmax, redm[j]);
    float lsum = 0.f;
    for (int k = t; k < Tc; k += 256) {
        float e = __expf(es[k] - bmax);
        es[k] = e;
        lsum += e;
    }
#pragma unroll
    for (int o = 16; o; o >>= 1) lsum += __shfl_xor_sync(~0u, lsum, o);
    if ((t & 31) == 0) reds[t >> 5] = lsum;
    __syncthreads();
    float bsum = 0.f;
#pragma unroll
    for (int j = 0; j < 8; ++j) bsum += reds[j];
    const float inv = 1.f / bsum;
    for (int k = t; k < Tc; k += 256) out[b * Tc + k] = es[k] * inv;
}

// =====================================================================
extern "C" void kernel_launch(void* const* d_in, const int* in_sizes, int n_in,
                              void* d_out, int out_size) {
    (void)in_sizes; (void)n_in; (void)out_size;
    const float* x    = (const float*)d_in[0];
    const float* mask = (const float*)d_in[1];
    const float* Wqkv = (const float*)d_in[2];
    const float* bqkv = (const float*)d_in[3];
    const float* Wo   = (const float*)d_in[4];
    const float* bo   = (const float*)d_in[5];
    const float* W1   = (const float*)d_in[6];
    const float* b1   = (const float*)d_in[7];
    const float* W2   = (const float*)d_in[8];
    const float* b2   = (const float*)d_in[9];
    const float* g1   = (const float*)d_in[10];
    const float* be1  = (const float*)d_in[11];
    const float* g2   = (const float*)d_in[12];
    const float* be2  = (const float*)d_in[13];
    float* out  = (float*)d_out;
    float* halt = out + (size_t)Bc * Tc * Dc;

    __half *p_xh, *p_qkvh, *p_attnh, *p_hh, *p_fh, *p_wqkvh, *p_woh, *p_w1h, *p_w2h;
    float *p_h;
    cudaGetSymbolAddress((void**)&p_xh, g_xh);
    cudaGetSymbolAddress((void**)&p_qkvh, g_qkvh);
    cudaGetSymbolAddress((void**)&p_attnh, g_attnh);
    cudaGetSymbolAddress((void**)&p_hh, g_hh);
    cudaGetSymbolAddress((void**)&p_fh, g_fh);
    cudaGetSymbolAddress((void**)&p_wqkvh, g_wqkvh);
    cudaGetSymbolAddress((void**)&p_woh, g_woh);
    cudaGetSymbolAddress((void**)&p_w1h, g_w1h);
    cudaGetSymbolAddress((void**)&p_w2h, g_w2h);
    cudaGetSymbolAddress((void**)&p_h, g_h);

    const int SMEM_128 = 65536;
    const int SMEM_AT  = 57344;   // Q16K + K2x8K + V2x8K + mask8K
    const int SMEM_LN  = 82432;
    cudaFuncSetAttribute(gemm_proj_k, cudaFuncAttributeMaxDynamicSharedMemorySize, SMEM_128);
    cudaFuncSetAttribute(attn2_k,     cudaFuncAttributeMaxDynamicSharedMemorySize, SMEM_AT);
    cudaFuncSetAttribute(gemm_ln_k,   cudaFuncAttributeMaxDynamicSharedMemorySize, SMEM_LN);

    const int MR = Bc * Tc;  // 16384

    pack_all<<<(SEG4 + 255) / 256, 256>>>(x, Wqkv, Wo, W1, W2);
    gemm_proj_k<<<dim3(6, MR / 128), 256, SMEM_128>>>(p_xh, p_wqkvh, bqkv, p_qkvh,
                                                      Dc, Dc, 3 * Dc, Dc, 0);
    vt_pack<<<dim3(Tc / 64, Bc * Hc), 256>>>(p_qkvh);
    attn2_k<<<dim3(Tc / 128, Bc * Hc), 256, SMEM_AT>>>(p_qkvh, mask);
    halting_k<<<Bc, 256>>>(mask, halt);
    gemm_ln_k<<<MR / 64, 256, SMEM_LN>>>(p_attnh, p_woh, bo, x, g1, be1, p_h, p_hh, Dc, Dc);
    gemm_proj_k<<<dim3(8, MR / 128), 256, SMEM_128>>>(p_hh, p_w1h, b1, p_fh,
                                                      Dc, Dc, FFNc, Dc, 1);
    gemm_ln_k<<<MR / 64, 256, SMEM_LN>>>(p_fh, p_w2h, b2, p_h, g2, be2, out, nullptr, FFNc, FFNc);
}

// round 9
// speedup vs baseline: 1.0603x; 1.0603x over previous
#include <cuda_runtime.h>
#include <cuda_fp16.h>
#include <cstdint>
#include <cstddef>

#define Bc 8
#define Tc 2048
#define Dc 256
#define Hc 4
#define FFNc 1024

// ---------------- scratch (static device arrays) ----------------
__device__ __half g_xh[(size_t)Bc * Tc * Dc];
__device__ __half g_qkvh[(size_t)Bc * Tc * 3 * Dc];
__device__ __half g_vth[(size_t)Bc * Hc * 64 * Tc];     // V^T fp16 [bh][d][k]
__device__ __half g_attnh[(size_t)Bc * Tc * Dc];
__device__ __half g_hh[(size_t)Bc * Tc * Dc];
__device__ __half g_fh[(size_t)Bc * Tc * FFNc];
__device__ __half g_wqkvh[3 * Dc * Dc];
__device__ __half g_woh[Dc * Dc];
__device__ __half g_w1h[FFNc * Dc];
__device__ __half g_w2h[Dc * FFNc];
__device__ float g_h[(size_t)Bc * Tc * Dc];
__device__ float g_hraw[Bc * Tc];

// ---------------- helpers ----------------
__device__ __forceinline__ uint32_t s2u(const void* p) {
    uint32_t a;
    asm("{ .reg .u64 t; cvta.to.shared.u64 t, %1; cvt.u32.u64 %0, t; }" : "=r"(a) : "l"(p));
    return a;
}
__device__ __forceinline__ float ex2(float x) {
    float r;
    asm("ex2.approx.ftz.f32 %0, %1;" : "=f"(r) : "f"(x));
    return r;
}
#define EXPC 0.18033688011112042f   // 0.125 * log2(e)
#define CP_ASYNC16(dst, src) \
    asm volatile("cp.async.cg.shared.global [%0], [%1], 16;" :: "r"(dst), "l"(src))

__device__ __forceinline__ void ldm_x4(uint32_t* r, uint32_t addr) {
    asm volatile("ldmatrix.sync.aligned.m8n8.x4.shared.b16 {%0,%1,%2,%3}, [%4];"
                 : "=r"(r[0]), "=r"(r[1]), "=r"(r[2]), "=r"(r[3]) : "r"(addr));
}
__device__ __forceinline__ void mma16816(float* c, const uint32_t* a, const uint32_t* b) {
    asm volatile("mma.sync.aligned.m16n8k16.row.col.f32.f16.f16.f32 "
                 "{%0,%1,%2,%3}, {%4,%5,%6,%7}, {%8,%9}, {%0,%1,%2,%3};"
                 : "+f"(c[0]), "+f"(c[1]), "+f"(c[2]), "+f"(c[3])
                 : "r"(a[0]), "r"(a[1]), "r"(a[2]), "r"(a[3]), "r"(b[0]), "r"(b[1]));
}

// S-tile: acc[4][2][4] += A(128x64 smem, swz rows of 128B) @ B(64x64 smem)^T
__device__ __forceinline__ void stile64(uint32_t As, uint32_t Bs, float (&acc)[4][2][4],
                                        int lane, int wm, int wn) {
#pragma unroll
    for (int ks = 0; ks < 4; ++ks) {
        const int ck = ks * 2 + (lane >> 4);
        uint32_t af[4][4];
#pragma unroll
        for (int mt = 0; mt < 4; ++mt) {
            int m = wm + mt * 16 + (lane & 15);
            ldm_x4(af[mt], As + m * 128 + ((ck ^ (m & 7)) << 4));
        }
        uint32_t bf[2][2];
        {
            uint32_t r4[4];
            int n = wn + (lane & 15);
            ldm_x4(r4, Bs + n * 128 + ((ck ^ (n & 7)) << 4));
            bf[0][0] = r4[0]; bf[0][1] = r4[2];
            bf[1][0] = r4[1]; bf[1][1] = r4[3];
        }
#pragma unroll
        for (int mt = 0; mt < 4; ++mt)
#pragma unroll
            for (int nt = 0; nt < 2; ++nt) mma16816(acc[mt][nt], af[mt], bf[nt]);
    }
}

// ---------------- merged attention: denominators, then normalized PV + colsum ----------------
// grid (16 q-tiles, 32 bh), 256 threads, 2 CTAs/SM.
// Loop A uses 128-row K tiles: one Q-fragment load feeds TWO 64-k sub-tiles.
__global__ __launch_bounds__(256, 2) void attn2_k(const __half* __restrict__ qkvh,
                                                  const float* __restrict__ mask) {
    extern __shared__ char sm[];
    const uint32_t S0 = s2u(sm);
    const uint32_t Qs = S0;                    // 16 KB
    const uint32_t Ks = S0 + 16384;            // loop A: 2 bufs x 16 KB; loop B: 2 bufs x 8 KB
    const uint32_t Vs = S0 + 49152;            // 2 bufs x 8 KB
    const uint32_t Es = S0 + 65536;            // 16 KB
    float* msk = (float*)(sm + 81920);         // 2048 floats: additive offsets 0 / -1000
    float* dsum = (float*)(sm + 90112);        // 128
    float* l2d_sm = (float*)(sm + 90624);      // 128: -log2(denominator)
    const int tid = threadIdx.x, lane = tid & 31, wid = tid >> 5;
    const int bh = blockIdx.y, b = bh >> 2, h = bh & 3;
    const int m0 = blockIdx.x * 128;
    const int wm = (wid >> 2) * 64, wn = (wid & 3) * 16;

    for (int i = tid; i < Tc; i += 256) msk[i] = (mask[b * Tc + i] > 0.5f) ? -1000.f : 0.f;
    if (tid < 128) dsum[tid] = 0.f;

    {   // Q tile (persistent)
        const __half* q0 = qkvh + ((size_t)(b * Tc + m0)) * 768 + h * 64;
#pragma unroll
        for (int i = 0; i < 4; ++i) {
            int ch = i * 256 + tid, r = ch >> 3, c = ch & 7;
            CP_ASYNC16(Qs + r * 128 + ((c ^ (r & 7)) << 4), q0 + (size_t)r * 768 + c * 8);
        }
    }
    // loop A loader: 128 k rows per buffer
    auto loadK2 = [&](int kt2, int buf) {
        const __half* kg = qkvh + ((size_t)(b * Tc + kt2 * 128)) * 768 + 256 + h * 64;
#pragma unroll
        for (int i = 0; i < 4; ++i) {
            int ch = i * 256 + tid, r = ch >> 3, c = ch & 7;
            CP_ASYNC16(Ks + buf * 16384 + r * 128 + ((c ^ (r & 7)) << 4), kg + (size_t)r * 768 + c * 8);
        }
    };
    // loop B loader: 64 k rows K + V
    auto loadKV = [&](int kt, int buf) {
        const int k0 = kt * 64;
        const __half* kg = qkvh + ((size_t)(b * Tc + k0)) * 768 + 256 + h * 64;
        const __half* vg = g_vth + (size_t)bh * 64 * Tc + k0;
#pragma unroll
        for (int i = 0; i < 2; ++i) {
            int ch = i * 256 + tid, r = ch >> 3, c = ch & 7;
            uint32_t off = r * 128 + ((c ^ (r & 7)) << 4);
            CP_ASYNC16(Ks + buf * 8192 + off, kg + (size_t)r * 768 + c * 8);
            CP_ASYNC16(Vs + buf * 8192 + off, vg + (size_t)r * Tc + c * 8);
        }
    };

    // ---- loop A: denominators only (paired sub-tiles, shared Q fragments) ----
    loadK2(0, 0);
    asm volatile("cp.async.commit_group;");
    float dacc[4][2];
#pragma unroll
    for (int mt = 0; mt < 4; ++mt) dacc[mt][0] = dacc[mt][1] = 0.f;

    const int cbase = wn + 2 * (lane & 3);
    for (int kt2 = 0; kt2 < 16; ++kt2) {
        const int buf = kt2 & 1;
        asm volatile("cp.async.wait_group 0;");
        __syncthreads();
        float sacc[2][4][2][4];
#pragma unroll
        for (int sub = 0; sub < 2; ++sub)
#pragma unroll
            for (int mt = 0; mt < 4; ++mt)
#pragma unroll
                for (int nt = 0; nt < 2; ++nt)
#pragma unroll
                    for (int i = 0; i < 4; ++i) sacc[sub][mt][nt][i] = 0.f;
        // paired S-tiles: load Q fragment once per (ks,mt), use for both sub-tiles
#pragma unroll
        for (int ks = 0; ks < 4; ++ks) {
            const int ck = ks * 2 + (lane >> 4);
            uint32_t af[4][4];
#pragma unroll
            for (int mt = 0; mt < 4; ++mt) {
                int m = wm + mt * 16 + (lane & 15);
                ldm_x4(af[mt], Qs + m * 128 + ((ck ^ (m & 7)) << 4));
            }
#pragma unroll
            for (int sub = 0; sub < 2; ++sub) {
                const uint32_t base = Ks + buf * 16384 + sub * 8192;
                uint32_t bf[2][2];
                {
                    uint32_t r4[4];
                    int n = wn + (lane & 15);
                    ldm_x4(r4, base + n * 128 + ((ck ^ (n & 7)) << 4));
                    bf[0][0] = r4[0]; bf[0][1] = r4[2];
                    bf[1][0] = r4[1]; bf[1][1] = r4[3];
                }
#pragma unroll
                for (int mt = 0; mt < 4; ++mt)
#pragma unroll
                    for (int nt = 0; nt < 2; ++nt) mma16816(sacc[sub][mt][nt], af[mt], bf[nt]);
            }
        }
        if (kt2 + 1 < 16) {
            loadK2(kt2 + 1, buf ^ 1);
            asm volatile("cp.async.commit_group;");
        }
#pragma unroll
        for (int sub = 0; sub < 2; ++sub) {
            const int k0 = kt2 * 128 + sub * 64;
            float mo[4] = {msk[k0 + cbase], msk[k0 + cbase + 1],
                           msk[k0 + cbase + 8], msk[k0 + cbase + 9]};
#pragma unroll
            for (int mt = 0; mt < 4; ++mt)
#pragma unroll
                for (int nt = 0; nt < 2; ++nt) {
                    dacc[mt][0] += ex2(fmaf(sacc[sub][mt][nt][0], EXPC, mo[2 * nt]))
                                 + ex2(fmaf(sacc[sub][mt][nt][1], EXPC, mo[2 * nt + 1]));
                    dacc[mt][1] += ex2(fmaf(sacc[sub][mt][nt][2], EXPC, mo[2 * nt]))
                                 + ex2(fmaf(sacc[sub][mt][nt][3], EXPC, mo[2 * nt + 1]));
                }
        }
    }
#pragma unroll
    for (int mt = 0; mt < 4; ++mt) {
        float d0 = dacc[mt][0], d1 = dacc[mt][1];
        d0 += __shfl_xor_sync(~0u, d0, 1); d0 += __shfl_xor_sync(~0u, d0, 2);
        d1 += __shfl_xor_sync(~0u, d1, 1); d1 += __shfl_xor_sync(~0u, d1, 2);
        if ((lane & 3) == 0) {
            atomicAdd(&dsum[wm + mt * 16 + (lane >> 2)], d0);
            atomicAdd(&dsum[wm + mt * 16 + (lane >> 2) + 8], d1);
        }
    }
    __syncthreads();
    if (tid < 128) l2d_sm[tid] = -__log2f(dsum[tid]);
    __syncthreads();

    float l2r0[4], l2r1[4];
#pragma unroll
    for (int mt = 0; mt < 4; ++mt) {
        const int r = wm + mt * 16 + (lane >> 2);
        l2r0[mt] = l2d_sm[r];
        l2r1[mt] = l2d_sm[r + 8];
    }

    // ---- loop B: normalized weights -> PV + halting colsum (exact R6) ----
    loadKV(0, 0);
    asm volatile("cp.async.commit_group;");
    float pacc[4][2][4];
#pragma unroll
    for (int mt = 0; mt < 4; ++mt)
#pragma unroll
        for (int nt = 0; nt < 2; ++nt)
#pragma unroll
            for (int i = 0; i < 4; ++i) pacc[mt][nt][i] = 0.f;

    for (int kt = 0; kt < 32; ++kt) {
        const int buf = kt & 1;
        asm volatile("cp.async.wait_group 0;");
        __syncthreads();
        float sacc[4][2][4];
#pragma unroll
        for (int mt = 0; mt < 4; ++mt)
#pragma unroll
            for (int nt = 0; nt < 2; ++nt)
#pragma unroll
                for (int i = 0; i < 4; ++i) sacc[mt][nt][i] = 0.f;
        stile64(Qs, Ks + buf * 8192, sacc, lane, wm, wn);
        if (kt + 1 < 32) {
            loadKV(kt + 1, buf ^ 1);
            asm volatile("cp.async.commit_group;");
        }
        const int k0 = kt * 64;
        float mo[4] = {msk[k0 + cbase], msk[k0 + cbase + 1],
                       msk[k0 + cbase + 8], msk[k0 + cbase + 9]};
        float cp[2][2] = {{0.f, 0.f}, {0.f, 0.f}};
#pragma unroll
        for (int mt = 0; mt < 4; ++mt) {
            const int r = wm + mt * 16 + (lane >> 2);
#pragma unroll
            for (int nt = 0; nt < 2; ++nt) {
                const int c = wn + nt * 8 + 2 * (lane & 3);
                float w0 = ex2(fmaf(sacc[mt][nt][0], EXPC, mo[2 * nt] + l2r0[mt]));
                float w1 = ex2(fmaf(sacc[mt][nt][1], EXPC, mo[2 * nt + 1] + l2r0[mt]));
                float w2 = ex2(fmaf(sacc[mt][nt][2], EXPC, mo[2 * nt] + l2r1[mt]));
                float w3 = ex2(fmaf(sacc[mt][nt][3], EXPC, mo[2 * nt + 1] + l2r1[mt]));
                cp[nt][0] += w0 + w2;
                cp[nt][1] += w1 + w3;
                const uint32_t chunk = (uint32_t)(c >> 3);
                const uint32_t rem = (uint32_t)((c * 2) & 15);
                uint32_t a0 = Es + r * 128 + ((chunk ^ (r & 7)) << 4) + rem;
                uint32_t a1 = Es + (r + 8) * 128 + ((chunk ^ ((r + 8) & 7)) << 4) + rem;
                __half2 h0 = __floats2half2_rn(w0, w1);
                __half2 h1 = __floats2half2_rn(w2, w3);
                asm volatile("st.shared.b32 [%0], %1;" :: "r"(a0), "r"(*(uint32_t*)&h0));
                asm volatile("st.shared.b32 [%0], %1;" :: "r"(a1), "r"(*(uint32_t*)&h1));
            }
        }
#pragma unroll
        for (int nt = 0; nt < 2; ++nt)
#pragma unroll
            for (int j = 0; j < 2; ++j) {
                float v = cp[nt][j];
                v += __shfl_xor_sync(~0u, v, 4);
                v += __shfl_xor_sync(~0u, v, 8);
                v += __shfl_xor_sync(~0u, v, 16);
                if (lane < 4) {
                    const int c = wn + nt * 8 + 2 * lane + j;
                    atomicAdd(&g_hraw[b * Tc + k0 + c], 0.25f * v);
                }
            }
        // E rows are shared across the 4 warps of a row-group -> full CTA barrier required
        __syncthreads();
        stile64(Es, Vs + buf * 8192, pacc, lane, wm, wn);
    }

    // pacc is already normalized
#pragma unroll
    for (int mt = 0; mt < 4; ++mt) {
        const int r = wm + mt * 16 + (lane >> 2);
#pragma unroll
        for (int nt = 0; nt < 2; ++nt) {
            const int c = wn + nt * 8 + 2 * (lane & 3);
            *(__half2*)(g_attnh + (size_t)(b * Tc + m0 + r) * Dc + h * 64 + c) =
                __floats2half2_rn(pacc[mt][nt][0], pacc[mt][nt][1]);
            *(__half2*)(g_attnh + (size_t)(b * Tc + m0 + r + 8) * Dc + h * 64 + c) =
                __floats2half2_rn(pacc[mt][nt][2], pacc[mt][nt][3]);
        }
    }
}

// ---------------- fp16 mma.sync GEMM core (BM=128, BN=128) ----------------
__device__ __forceinline__ void gemm_core128(const __half* __restrict__ Ag, int lda,
                                             const __half* __restrict__ Bg, int ldb,
                                             int K, int m0, int n0,
                                             float (&acc)[4][4][4]) {
    extern __shared__ char smem_raw[];
    const int tid = threadIdx.x, lane = tid & 31, wid = tid >> 5;
    const int wm = (wid >> 2) * 64;
    const int wn = (wid & 3) * 32;
    const uint32_t sA = s2u(smem_raw);
    const uint32_t sB = sA + 2 * 128 * 128;
    const int NKT = K >> 6;

#pragma unroll
    for (int mt = 0; mt < 4; ++mt)
#pragma unroll
        for (int nt = 0; nt < 4; ++nt)
#pragma unroll
            for (int i = 0; i < 4; ++i) acc[mt][nt][i] = 0.f;

    auto loadA = [&](int kt, int buf) {
        const __half* s0 = Ag + (size_t)m0 * lda + kt * 64;
        uint32_t d0 = sA + buf * (128 * 128);
#pragma unroll
        for (int i = 0; i < 4; ++i) {
            int ch = i * 256 + tid, r = ch >> 3, c = ch & 7;
            CP_ASYNC16(d0 + r * 128 + ((c ^ (r & 7)) << 4), s0 + (size_t)r * lda + c * 8);
        }
    };
    auto loadB = [&](int kt, int buf) {
        const __half* s0 = Bg + (size_t)n0 * ldb + kt * 64;
        uint32_t d0 = sB + buf * (128 * 128);
#pragma unroll
        for (int i = 0; i < 4; ++i) {
            int ch = i * 256 + tid, r = ch >> 3, c = ch & 7;
            CP_ASYNC16(d0 + r * 128 + ((c ^ (r & 7)) << 4), s0 + (size_t)r * ldb + c * 8);
        }
    };

    loadA(0, 0); loadB(0, 0);
    asm volatile("cp.async.commit_group;");

    for (int t = 0; t < NKT; ++t) {
        const int buf = t & 1;
        if (t + 1 < NKT) {
            loadA(t + 1, buf ^ 1); loadB(t + 1, buf ^ 1);
            asm volatile("cp.async.commit_group;");
            asm volatile("cp.async.wait_group 1;");
        } else {
            asm volatile("cp.async.wait_group 0;");
        }
        __syncthreads();
        const uint32_t cA = sA + buf * (128 * 128);
        const uint32_t cB = sB + buf * (128 * 128);
#pragma unroll
        for (int ks = 0; ks < 4; ++ks) {
            uint32_t af[4][4];
#pragma unroll
            for (int mt = 0; mt < 4; ++mt) {
                int m = wm + mt * 16 + (lane & 15);
                int ck = ks * 2 + (lane >> 4);
                ldm_x4(af[mt], cA + m * 128 + ((ck ^ (m & 7)) << 4));
            }
            uint32_t bf[4][2];
#pragma unroll
            for (int g = 0; g < 2; ++g) {
                uint32_t r4[4];
                int n = wn + g * 16 + (lane & 15);
                int ck = ks * 2 + (lane >> 4);
                ldm_x4(r4, cB + n * 128 + ((ck ^ (n & 7)) << 4));
                bf[2 * g][0] = r4[0]; bf[2 * g][1] = r4[2];
                bf[2 * g + 1][0] = r4[1]; bf[2 * g + 1][1] = r4[3];
            }
#pragma unroll
            for (int mt = 0; mt < 4; ++mt)
#pragma unroll
                for (int nt = 0; nt < 4; ++nt) mma16816(acc[mt][nt], af[mt], bf[nt]);
        }
        __syncthreads();
    }
}

__global__ __launch_bounds__(256) void gemm_proj_k(const __half* __restrict__ A,
                                                   const __half* __restrict__ Bw,
                                                   const float* __restrict__ bias,
                                                   __half* __restrict__ Ch,
                                                   int lda, int ldb, int ldc, int K, int relu) {
    float acc[4][4][4];
    const int m0 = blockIdx.y * 128, n0 = blockIdx.x * 128;
    gemm_core128(A, lda, Bw, ldb, K, m0, n0, acc);
    const int lane = threadIdx.x & 31, wid = threadIdx.x >> 5;
    const int wm = (wid >> 2) * 64, wn = (wid & 3) * 32;
#pragma unroll
    for (int mt = 0; mt < 4; ++mt) {
        int r = m0 + wm + mt * 16 + (lane >> 2);
#pragma unroll
        for (int nt = 0; nt < 4; ++nt) {
            int col = n0 + wn + nt * 8 + 2 * (lane & 3);
            float bx = __ldg(bias + col), by = __ldg(bias + col + 1);
            float v0 = acc[mt][nt][0] + bx, v1 = acc[mt][nt][1] + by;
            float v2 = acc[mt][nt][2] + bx, v3 = acc[mt][nt][3] + by;
            if (relu) {
                v0 = fmaxf(v0, 0.f); v1 = fmaxf(v1, 0.f);
                v2 = fmaxf(v2, 0.f); v3 = fmaxf(v3, 0.f);
            }
            *(__half2*)(Ch + (size_t)r * ldc + col) = __floats2half2_rn(v0, v1);
            *(__half2*)(Ch + (size_t)(r + 8) * ldc + col) = __floats2half2_rn(v2, v3);
        }
    }
}

// ---------------- GEMM (BM=64, BN=256=N) + bias + residual + LayerNorm ----------------
__global__ __launch_bounds__(256) void gemm_ln_k(const __half* __restrict__ A,
                                                 const __half* __restrict__ Bw,
                                                 const float* __restrict__ bias,
                                                 const float* __restrict__ res,
                                                 const float* __restrict__ gamma,
                                                 const float* __restrict__ beta,
                                                 float* __restrict__ outf,
                                                 __half* __restrict__ outh,
                                                 int lda, int K) {
    extern __shared__ char sm[];
    const uint32_t sA = s2u(sm);               // 2 x 8192
    const uint32_t sB = sA + 16384;            // 2 x 32768
    float* sred = (float*)(sm + 16384 + 65536);
    float* sqred = sred + 64;
    const int tid = threadIdx.x, lane = tid & 31, wid = tid >> 5;
    const int m0 = blockIdx.x * 64;
    const int wm = (wid >> 2) * 32, wn = (wid & 3) * 64;
    const int NKT = K >> 6;

    float acc[2][8][4];
#pragma unroll
    for (int mt = 0; mt < 2; ++mt)
#pragma unroll
        for (int nt = 0; nt < 8; ++nt)
#pragma unroll
            for (int i = 0; i < 4; ++i) acc[mt][nt][i] = 0.f;

    auto loadA = [&](int kt, int buf) {
        const __half* s0 = A + (size_t)m0 * lda + kt * 64;
        uint32_t d0 = sA + buf * 8192;
#pragma unroll
        for (int i = 0; i < 2; ++i) {
            int ch = i * 256 + tid, r = ch >> 3, c = ch & 7;
            CP_ASYNC16(d0 + r * 128 + ((c ^ (r & 7)) << 4), s0 + (size_t)r * lda + c * 8);
        }
    };
    auto loadB = [&](int kt, int buf) {
        const __half* s0 = Bw + kt * 64;
        uint32_t d0 = sB + buf * 32768;
#pragma unroll
        for (int i = 0; i < 8; ++i) {
            int ch = i * 256 + tid, r = ch >> 3, c = ch & 7;
            CP_ASYNC16(d0 + r * 128 + ((c ^ (r & 7)) << 4), s0 + (size_t)r * K + c * 8);
        }
    };

    loadA(0, 0); loadB(0, 0);
    asm volatile("cp.async.commit_group;");

    for (int t = 0; t < NKT; ++t) {
        const int buf = t & 1;
        if (t + 1 < NKT) {
            loadA(t + 1, buf ^ 1); loadB(t + 1, buf ^ 1);
            asm volatile("cp.async.commit_group;");
            asm volatile("cp.async.wait_group 1;");
        } else {
            asm volatile("cp.async.wait_group 0;");
        }
        __syncthreads();
        const uint32_t cA = sA + buf * 8192;
        const uint32_t cB = sB + buf * 32768;
#pragma unroll
        for (int ks = 0; ks < 4; ++ks) {
            const int ck = ks * 2 + (lane >> 4);
            uint32_t af[2][4];
#pragma unroll
            for (int mt = 0; mt < 2; ++mt) {
                int m = wm + mt * 16 + (lane & 15);
                ldm_x4(af[mt], cA + m * 128 + ((ck ^ (m & 7)) << 4));
            }
            uint32_t bf[8][2];
#pragma unroll
            for (int g = 0; g < 4; ++g) {
                uint32_t r4[4];
                int n = wn + g * 16 + (lane & 15);
                ldm_x4(r4, cB + n * 128 + ((ck ^ (n & 7)) << 4));
                bf[2 * g][0] = r4[0]; bf[2 * g][1] = r4[2];
                bf[2 * g + 1][0] = r4[1]; bf[2 * g + 1][1] = r4[3];
            }
#pragma unroll
            for (int mt = 0; mt < 2; ++mt)
#pragma unroll
                for (int nt = 0; nt < 8; ++nt) mma16816(acc[mt][nt], af[mt], bf[nt]);
        }
        __syncthreads();
    }

    // ---- epilogue: bias + residual, LN stats, normalize ----
    if (tid < 64) { sred[tid] = 0.f; sqred[tid] = 0.f; }
    __syncthreads();
#pragma unroll
    for (int mt = 0; mt < 2; ++mt) {
        const int r = wm + mt * 16 + (lane >> 2);
        float s0 = 0.f, sq0 = 0.f, s1 = 0.f, sq1 = 0.f;
#pragma unroll
        for (int nt = 0; nt < 8; ++nt) {
            const int col = wn + nt * 8 + 2 * (lane & 3);
            float bx = __ldg(bias + col), by = __ldg(bias + col + 1);
            float2 r0 = *(const float2*)(res + (size_t)(m0 + r) * Dc + col);
            float2 r1 = *(const float2*)(res + (size_t)(m0 + r + 8) * Dc + col);
            float v0 = acc[mt][nt][0] + bx + r0.x;
            float v1 = acc[mt][nt][1] + by + r0.y;
            float v2 = acc[mt][nt][2] + bx + r1.x;
            float v3 = acc[mt][nt][3] + by + r1.y;
            acc[mt][nt][0] = v0; acc[mt][nt][1] = v1;
            acc[mt][nt][2] = v2; acc[mt][nt][3] = v3;
            s0 += v0 + v1; sq0 += v0 * v0 + v1 * v1;
            s1 += v2 + v3; sq1 += v2 * v2 + v3 * v3;
        }
        s0 += __shfl_xor_sync(~0u, s0, 1); s0 += __shfl_xor_sync(~0u, s0, 2);
        sq0 += __shfl_xor_sync(~0u, sq0, 1); sq0 += __shfl_xor_sync(~0u, sq0, 2);
        s1 += __shfl_xor_sync(~0u, s1, 1); s1 += __shfl_xor_sync(~0u, s1, 2);
        sq1 += __shfl_xor_sync(~0u, sq1, 1); sq1 += __shfl_xor_sync(~0u, sq1, 2);
        if ((lane & 3) == 0) {
            atomicAdd(&sred[r], s0); atomicAdd(&sqred[r], sq0);
            atomicAdd(&sred[r + 8], s1); atomicAdd(&sqred[r + 8], sq1);
        }
    }
    __syncthreads();
#pragma unroll
    for (int mt = 0; mt < 2; ++mt) {
        const int r = wm + mt * 16 + (lane >> 2);
        const float mean0 = sred[r] * (1.f / Dc);
        const float rstd0 = rsqrtf(sqred[r] * (1.f / Dc) - mean0 * mean0 + 1e-5f);
        const float mean1 = sred[r + 8] * (1.f / Dc);
        const float rstd1 = rsqrtf(sqred[r + 8] * (1.f / Dc) - mean1 * mean1 + 1e-5f);
#pragma unroll
        for (int nt = 0; nt < 8; ++nt) {
            const int col = wn + nt * 8 + 2 * (lane & 3);
            float gx = __ldg(gamma + col), gy = __ldg(gamma + col + 1);
            float bx = __ldg(beta + col), by = __ldg(beta + col + 1);
            float o0 = (acc[mt][nt][0] - mean0) * rstd0 * gx + bx;
            float o1 = (acc[mt][nt][1] - mean0) * rstd0 * gy + by;
            float o2 = (acc[mt][nt][2] - mean1) * rstd1 * gx + bx;
            float o3 = (acc[mt][nt][3] - mean1) * rstd1 * gy + by;
            *(float2*)(outf + (size_t)(m0 + r) * Dc + col) = make_float2(o0, o1);
            *(float2*)(outf + (size_t)(m0 + r + 8) * Dc + col) = make_float2(o2, o3);
            if (outh) {
                *(__half2*)(outh + (size_t)(m0 + r) * Dc + col) = __floats2half2_rn(o0, o1);
                *(__half2*)(outh + (size_t)(m0 + r + 8) * Dc + col) = __floats2half2_rn(o2, o3);
            }
        }
    }
}

// ---------------- V transpose ----------------
__global__ __launch_bounds__(256) void vt_pack(const __half* __restrict__ qkvh) {
    __shared__ __half tile[64][72];
    const int bh = blockIdx.y, b = bh >> 2, h = bh & 3;
    const int k0 = blockIdx.x * 64;
    const int t = threadIdx.x;
#pragma unroll
    for (int i = 0; i < 16; ++i) {
        int idx = t + i * 256, kk = idx >> 6, d = idx & 63;
        tile[kk][d] = qkvh[(size_t)(b * Tc + k0 + kk) * 768 + 512 + h * 64 + d];
    }
    __syncthreads();
#pragma unroll
    for (int i = 0; i < 16; ++i) {
        int idx = t + i * 256, d = idx >> 6, kk = idx & 63;
        g_vth[(size_t)bh * 64 * Tc + (size_t)d * Tc + k0 + kk] = tile[kk][d];
    }
}

// ---------------- one merged pack kernel ----------------
#define SEG0 2097152u
#define SEG1 2195456u
#define SEG2 2228224u
#define SEG3 2359296u
#define SEG4 2490368u
__global__ __launch_bounds__(256) void pack_all(const float* __restrict__ x,
                                                const float* __restrict__ Wqkv,
                                                const float* __restrict__ Wo,
                                                const float* __restrict__ W1,
                                                const float* __restrict__ W2) {
    uint32_t i = blockIdx.x * 256 + threadIdx.x;
    if (i < Bc * Tc / 2) ((float2*)g_hraw)[i] = make_float2(0.f, 0.f);
    const float2* s;
    __half2* d;
    uint32_t off;
    if (i < SEG0)      { s = (const float2*)x;    d = (__half2*)g_xh;    off = i; }
    else if (i < SEG1) { s = (const float2*)Wqkv; d = (__half2*)g_wqkvh; off = i - SEG0; }
    else if (i < SEG2) { s = (const float2*)Wo;   d = (__half2*)g_woh;   off = i - SEG1; }
    else if (i < SEG3) { s = (const float2*)W1;   d = (__half2*)g_w1h;   off = i - SEG2; }
    else if (i < SEG4) { s = (const float2*)W2;   d = (__half2*)g_w2h;   off = i - SEG3; }
    else return;
    float2 v = s[off];
    d[off] = __floats2half2_rn(v.x, v.y);
}

__global__ __launch_bounds__(256) void halting_k(const float* __restrict__ mask, float* __restrict__ out) {
    const int b = blockIdx.x;
    const int t = threadIdx.x;
    __shared__ float es[Tc];
    __shared__ float redm[8], reds[8];
    float lmax = -3.4e38f;
    for (int k = t; k < Tc; k += 256) {
        float v = g_hraw[b * Tc + k] + mask[b * Tc + k] * (-1e10f);
        es[k] = v;
        lmax = fmaxf(lmax, v);
    }
#pragma unroll
    for (int o = 16; o; o >>= 1) lmax = fmaxf(lmax, __shfl_xor_sync(~0u, lmax, o));
    if ((t & 31) == 0) redm[t >> 5] = lmax;
    __syncthreads();
    float bmax = redm[0];
#pragma unroll
    for (int j = 1; j < 8; ++j) bmax = fmaxf(bmax, redm[j]);
    float lsum = 0.f;
    for (int k = t; k < Tc; k += 256) {
        float e = __expf(es[k] - bmax);
        es[k] = e;
        lsum += e;
    }
#pragma unroll
    for (int o = 16; o; o >>= 1) lsum += __shfl_xor_sync(~0u, lsum, o);
    if ((t & 31) == 0) reds[t >> 5] = lsum;
    __syncthreads();
    float bsum = 0.f;
#pragma unroll
    for (int j = 0; j < 8; ++j) bsum += reds[j];
    const float inv = 1.f / bsum;
    for (int k = t; k < Tc; k += 256) out[b * Tc + k] = es[k] * inv;
}

// =====================================================================
extern "C" void kernel_launch(void* const* d_in, const int* in_sizes, int n_in,
                              void* d_out, int out_size) {
    (void)in_sizes; (void)n_in; (void)out_size;
    const float* x    = (const float*)d_in[0];
    const float* mask = (const float*)d_in[1];
    const float* Wqkv = (const float*)d_in[2];
    const float* bqkv = (const float*)d_in[3];
    const float* Wo   = (const float*)d_in[4];
    const float* bo   = (const float*)d_in[5];
    const float* W1   = (const float*)d_in[6];
    const float* b1   = (const float*)d_in[7];
    const float* W2   = (const float*)d_in[8];
    const float* b2   = (const float*)d_in[9];
    const float* g1   = (const float*)d_in[10];
    const float* be1  = (const float*)d_in[11];
    const float* g2   = (const float*)d_in[12];
    const float* be2  = (const float*)d_in[13];
    float* out  = (float*)d_out;
    float* halt = out + (size_t)Bc * Tc * Dc;

    __half *p_xh, *p_qkvh, *p_attnh, *p_hh, *p_fh, *p_wqkvh, *p_woh, *p_w1h, *p_w2h;
    float *p_h;
    cudaGetSymbolAddress((void**)&p_xh, g_xh);
    cudaGetSymbolAddress((void**)&p_qkvh, g_qkvh);
    cudaGetSymbolAddress((void**)&p_attnh, g_attnh);
    cudaGetSymbolAddress((void**)&p_hh, g_hh);
    cudaGetSymbolAddress((void**)&p_fh, g_fh);
    cudaGetSymbolAddress((void**)&p_wqkvh, g_wqkvh);
    cudaGetSymbolAddress((void**)&p_woh, g_woh);
    cudaGetSymbolAddress((void**)&p_w1h, g_w1h);
    cudaGetSymbolAddress((void**)&p_w2h, g_w2h);
    cudaGetSymbolAddress((void**)&p_h, g_h);

    const int SMEM_128 = 65536;
    const int SMEM_AT  = 91136;   // Q16K + K32K + V16K + E16K + mask8K + red 1K
    const int SMEM_LN  = 82432;
    cudaFuncSetAttribute(gemm_proj_k, cudaFuncAttributeMaxDynamicSharedMemorySize, SMEM_128);
    cudaFuncSetAttribute(attn2_k,     cudaFuncAttributeMaxDynamicSharedMemorySize, SMEM_AT);
    cudaFuncSetAttribute(gemm_ln_k,   cudaFuncAttributeMaxDynamicSharedMemorySize, SMEM_LN);

    const int MR = Bc * Tc;  // 16384

    pack_all<<<(SEG4 + 255) / 256, 256>>>(x, Wqkv, Wo, W1, W2);
    gemm_proj_k<<<dim3(6, MR / 128), 256, SMEM_128>>>(p_xh, p_wqkvh, bqkv, p_qkvh,
                                                      Dc, Dc, 3 * Dc, Dc, 0);
    vt_pack<<<dim3(Tc / 64, Bc * Hc), 256>>>(p_qkvh);
    attn2_k<<<dim3(Tc / 128, Bc * Hc), 256, SMEM_AT>>>(p_qkvh, mask);
    halting_k<<<Bc, 256>>>(mask, halt);
    gemm_ln_k<<<MR / 64, 256, SMEM_LN>>>(p_attnh, p_woh, bo, x, g1, be1, p_h, p_hh, Dc, Dc);
    gemm_proj_k<<<dim3(8, MR / 128), 256, SMEM_128>>>(p_hh, p_w1h, b1, p_fh,
                                                      Dc, Dc, FFNc, Dc, 1);
    gemm_ln_k<<<MR / 64, 256, SMEM_LN>>>(p_fh, p_w2h, b2, p_h, g2, be2, out, nullptr, FFNc, FFNc);
}